// round 5
// baseline (speedup 1.0000x reference)
#include <cuda_runtime.h>
#include <cuda_fp16.h>
#include <cstdint>

static constexpr int N_TILES = 8192;   // 16 (w) x 128 (h) x 4 (batch)

#define MMA16816(c, a0, a1, a2, a3, b0, b1) \
    asm volatile( \
        "mma.sync.aligned.m16n8k16.row.col.f32.f16.f16.f32 " \
        "{%0,%1,%2,%3}, {%4,%5,%6,%7}, {%8,%9}, {%0,%1,%2,%3};" \
        : "+f"((c)[0]), "+f"((c)[1]), "+f"((c)[2]), "+f"((c)[3]) \
        : "r"(a0), "r"(a1), "r"(a2), "r"(a3), "r"(b0), "r"(b1))

__global__ __launch_bounds__(128, 3)
void depconv_hmma(const float* __restrict__ feat,
                  const int* __restrict__ depth,
                  const float* __restrict__ wgt,
                  float* __restrict__ out) {
    // ftile[pix][ch]: pix = r*34+cc (6x34 halo), 16 fp16 channels (32B/pixel)
    __shared__ __align__(16) unsigned short ftile[204 * 16];     // 6528 B
    // Bsm[ks][n][ch]: ks = t*2+s (18), n = oc (32), ch = ic (16)
    __shared__ __align__(16) unsigned short Bsm[18 * 32 * 16];   // 18432 B
    __shared__ int dt[204];                                      // 816 B
    __shared__ int csm[128];                                     // gating codes

    const int tid  = threadIdx.x;
    const int wid  = tid >> 5;
    const int lane = tid & 31;
    const int g    = lane >> 2;       // fragment group 0..7
    const int t4   = lane & 3;

    const int ochalf = wid & 1;       // warp owns 16 oc
    const int rp     = wid >> 1;      // warp owns row pair (2 rows x 32 cols = 64 px)

    // ---- build B once per CTA (fp16) ----
    for (int idx = tid; idx < 9216; idx += 128) {
        int ks = idx >> 9, rem = idx & 511;
        int n = rem >> 4, i = rem & 15;
        int t = ks >> 1, s = ks & 1;
        float v = wgt[(n * 16 + i) * 27 + s * 9 + t];
        Bsm[idx] = __half_as_ushort(__float2half_rn(v));
    }
    __syncthreads();

    const char* fb = (const char*)ftile;
    const char* Bb = (const char*)Bsm;

    // ---- hoist this warp's B fragments into registers (once per kernel) ----
    uint2 bv[18][2];
    #pragma unroll
    for (int ks = 0; ks < 18; ks++)
        #pragma unroll
        for (int nt = 0; nt < 2; nt++)
            bv[ks][nt] = *(const uint2*)(Bb + ks * 1024 +
                                         (ochalf * 16 + nt * 8 + g) * 32 + t4 * 8);

    // thread-constant A base addrs: mtile mt -> row rp*2+(mt>>1), col (mt&1)*16+g
    uint32_t aBase[4];
    #pragma unroll
    for (int mt = 0; mt < 4; mt++)
        aBase[mt] = (uint32_t)((((rp * 2 + (mt >> 1)) * 34) +
                                (mt & 1) * 16 + g) * 32 + t4 * 8);

    const int ic2 = lane & 7;     // channel-pair for staging
    const int pf  = lane >> 3;    // pixel offset 0..3 for staging

    for (int tile = blockIdx.x; tile < N_TILES; tile += gridDim.x) {
        const int twi = tile & 15, thi = (tile >> 4) & 127, b = tile >> 11;
        const int h0 = thi * 4, w0 = twi * 32;

        // ---- stage depth halo (6 x 34) ----
        for (int idx = tid; idx < 204; idx += 128) {
            int r = idx / 34, cc = idx - r * 34;
            int h = h0 - 1 + r, w = w0 - 1 + cc;
            int v = 0;
            if ((unsigned)h < 512u && (unsigned)w < 512u)
                v = depth[(b * 512 + h) * 512 + w];
            dt[idx] = v;
        }
        // ---- stage features as fp16 pairs; bank-conflict-free STS.32 ----
        {
            const float* fp0 = feat + ((size_t)b * 16 + 2 * ic2) * 262144;
            for (int base = wid * 4; base < 204; base += 16) {
                int pix = base + pf;
                int r = pix / 34, cc = pix - r * 34;
                int h = h0 - 1 + r, w = w0 - 1 + cc;
                float v0 = 0.f, v1 = 0.f;
                if ((unsigned)h < 512u && (unsigned)w < 512u) {
                    v0 = fp0[h * 512 + w];
                    v1 = fp0[262144 + h * 512 + w];
                }
                __half2 hv = __floats2half2_rn(v0, v1);
                *(uint32_t*)((char*)ftile + pix * 32 + ic2 * 4) =
                    *reinterpret_cast<uint32_t*>(&hv);
            }
        }
        __syncthreads();

        // ---- cooperative gating codes: thread tid handles pixel tid ----
        {
            int row = tid >> 5, col = tid & 31;
            int dcc = dt[(row + 1) * 34 + col + 1];
            int A = 0, Bc = 0;
            #pragma unroll
            for (int t = 0; t < 9; t++) {
                int dn = dt[(row + t / 3) * 34 + col + t % 3];
                int diff = dn - dcc;
                A  |= (diff == -1) ? (1 << t) : 0;
                Bc |= (diff == 0) ? (1 << t) : 0;
            }
            csm[tid] = A | (Bc << 16);
        }
        __syncthreads();

        // fetch this thread's 8 pixel codes
        int code[4][2];
        #pragma unroll
        for (int mt = 0; mt < 4; mt++) {
            int base = (rp * 2 + (mt >> 1)) * 32 + (mt & 1) * 16 + g;
            code[mt][0] = csm[base];
            code[mt][1] = csm[base + 8];
        }

        float acc[4][2][4];
        #pragma unroll
        for (int mt = 0; mt < 4; mt++)
            #pragma unroll
            for (int nt = 0; nt < 2; nt++)
                #pragma unroll
                for (int j = 0; j < 4; j++) acc[mt][nt][j] = 0.f;

        // ---- K loop: 9 taps x 2 slices, base+imm LDS, B from registers ----
        #pragma unroll
        for (int t = 0; t < 9; t++) {
            const int dOff = ((t / 3) * 34 + (t % 3)) * 32;
            uint2 x0[4], x1[4];
            #pragma unroll
            for (int mt = 0; mt < 4; mt++) {
                x0[mt] = *(const uint2*)(fb + aBase[mt] + dOff);
                x1[mt] = *(const uint2*)(fb + aBase[mt] + dOff + 256);
            }
            #pragma unroll
            for (int s = 0; s < 2; s++) {
                const int ks = t * 2 + s;
                #pragma unroll
                for (int mt = 0; mt < 4; mt++) {
                    uint32_t m0 = (uint32_t)(-((code[mt][0] >> (t + 16 * s)) & 1));
                    uint32_t m1 = (uint32_t)(-((code[mt][1] >> (t + 16 * s)) & 1));
                    uint32_t a0 = x0[mt].x & m0;
                    uint32_t a1 = x1[mt].x & m1;
                    uint32_t a2 = x0[mt].y & m0;
                    uint32_t a3 = x1[mt].y & m1;
                    MMA16816(acc[mt][0], a0, a1, a2, a3, bv[ks][0].x, bv[ks][0].y);
                    MMA16816(acc[mt][1], a0, a1, a2, a3, bv[ks][1].x, bv[ks][1].y);
                }
            }
        }

        // ---- epilogue: direct STG (8-lane 32B sectors) ----
        #pragma unroll
        for (int mt = 0; mt < 4; mt++) {
            const int h = h0 + rp * 2 + (mt >> 1);
            const int wpx = w0 + (mt & 1) * 16 + g;
            #pragma unroll
            for (int nt = 0; nt < 2; nt++) {
                int oc = ochalf * 16 + nt * 8 + t4 * 2;
                float* op = out + (((size_t)b * 32 + oc) * 512 + h) * 512;
                op[wpx]              = acc[mt][nt][0];
                op[262144 + wpx]     = acc[mt][nt][1];
                op[wpx + 8]          = acc[mt][nt][2];
                op[262144 + wpx + 8] = acc[mt][nt][3];
            }
        }
        __syncthreads();   // ftile/dt/csm free before next tile's staging
    }
}

extern "C" void kernel_launch(void* const* d_in, const int* in_sizes, int n_in,
                              void* d_out, int out_size) {
    const float* feat  = (const float*)d_in[0];   // (4,16,512,512) f32
    const int*   depth = (const int*)d_in[1];     // (4,512,512) i32
    const float* wgt   = (const float*)d_in[2];   // (32,16,3,3,3) f32
    float* out = (float*)d_out;                   // (4,32,512,512) f32

    int dev = 0, sms = 148;
    cudaGetDevice(&dev);
    cudaDeviceGetAttribute(&sms, cudaDevAttrMultiProcessorCount, dev);
    int grid = 3 * sms;
    if (grid > N_TILES) grid = N_TILES;
    depconv_hmma<<<grid, 128>>>(feat, depth, wgt, out);
}

// round 7
// speedup vs baseline: 1.0371x; 1.0371x over previous
#include <cuda_runtime.h>
#include <cuda_fp16.h>
#include <cstdint>

static constexpr int N_TILES = 8192;   // 16 (w) x 128 (h) x 4 (batch)

#define MMA16816(c, a0, a1, a2, a3, b0, b1) \
    asm volatile( \
        "mma.sync.aligned.m16n8k16.row.col.f32.f16.f16.f32 " \
        "{%0,%1,%2,%3}, {%4,%5,%6,%7}, {%8,%9}, {%0,%1,%2,%3};" \
        : "+f"((c)[0]), "+f"((c)[1]), "+f"((c)[2]), "+f"((c)[3]) \
        : "r"(a0), "r"(a1), "r"(a2), "r"(a3), "r"(b0), "r"(b1))

__global__ __launch_bounds__(256, 3)
void depconv_hmma(const float* __restrict__ feat,
                  const int* __restrict__ depth,
                  const float* __restrict__ wgt,
                  float* __restrict__ out) {
    // ftile[pix][ch]: pix = r*34+cc (6x34 halo), 16 fp16 channels (32B/pixel)
    __shared__ __align__(16) unsigned short ftile[204 * 16];     // 6528 B
    // Bsm[ks][n][ch]: ks = t*2+s (18), n = oc (32), ch = ic (16)
    __shared__ __align__(16) unsigned short Bsm[18 * 32 * 16];   // 18432 B
    __shared__ int dt[204];                                      // 816 B

    const int tid  = threadIdx.x;
    const int wid  = tid >> 5;        // 8 warps
    const int lane = tid & 31;
    const int g    = lane >> 2;       // fragment group 0..7
    const int t4   = lane & 3;

    const int row     = wid >> 1;     // tile row 0..3
    const int colhalf = wid & 1;      // 16-px half-row

    // ---- build B once per CTA (fp16) ----
    for (int idx = tid; idx < 9216; idx += 256) {
        int ks = idx >> 9, rem = idx & 511;
        int n = rem >> 4, i = rem & 15;
        int t = ks >> 1, s = ks & 1;
        float v = wgt[(n * 16 + i) * 27 + s * 9 + t];
        Bsm[idx] = __half_as_ushort(__float2half_rn(v));
    }
    __syncthreads();

    const char* fb = (const char*)ftile;
    const char* Bb = (const char*)Bsm;

    // Warp owns pixels (row, colhalf*16 + 0..15); thread's two rows: g, g+8
    const uint32_t aBase =
        (uint32_t)(((row * 34) + colhalf * 16 + g) * 32 + t4 * 8);
    const uint32_t bBase = (uint32_t)(g * 32 + t4 * 8);

    const int ic2 = tid & 7;      // channel-pair for staging
    const int pr  = tid >> 3;     // pixel lane 0..31 for staging

    for (int tile = blockIdx.x; tile < N_TILES; tile += gridDim.x) {
        const int twi = tile & 15, thi = (tile >> 4) & 127, b = tile >> 11;
        const int h0 = thi * 4, w0 = twi * 32;

        // ---- stage depth halo (6 x 34) ----
        if (tid < 204) {
            int r = tid / 34, cc = tid - r * 34;
            int h = h0 - 1 + r, w = w0 - 1 + cc;
            int v = 0;
            if ((unsigned)h < 512u && (unsigned)w < 512u)
                v = depth[(b * 512 + h) * 512 + w];
            dt[tid] = v;
        }
        // ---- stage features as fp16 pairs; 32 pixel-lanes x 8 ch-pairs ----
        {
            const float* fp0 = feat + ((size_t)b * 16 + 2 * ic2) * 262144;
            #pragma unroll
            for (int pix = pr; pix < 204; pix += 32) {
                int r = pix / 34, cc = pix - r * 34;
                int h = h0 - 1 + r, w = w0 - 1 + cc;
                float v0 = 0.f, v1 = 0.f;
                if ((unsigned)h < 512u && (unsigned)w < 512u) {
                    v0 = fp0[h * 512 + w];
                    v1 = fp0[262144 + h * 512 + w];
                }
                __half2 hv = __floats2half2_rn(v0, v1);
                *(uint32_t*)((char*)ftile + pix * 32 + ic2 * 4) =
                    *reinterpret_cast<uint32_t*>(&hv);
            }
        }
        __syncthreads();

        // ---- gating codes for this thread's 2 pixels (rows g, g+8) ----
        int code[2];
        #pragma unroll
        for (int p = 0; p < 2; p++) {
            int pc = colhalf * 16 + g + p * 8;
            int dcc = dt[(row + 1) * 34 + pc + 1];
            int A = 0, Bc = 0;
            #pragma unroll
            for (int t = 0; t < 9; t++) {
                int dn = dt[(row + t / 3) * 34 + pc + t % 3];
                int diff = dn - dcc;
                A  |= (diff == -1) ? (1 << t) : 0;
                Bc |= (diff == 0) ? (1 << t) : 0;
            }
            code[p] = A | (Bc << 16);
        }

        float acc[4][4];
        #pragma unroll
        for (int nt = 0; nt < 4; nt++)
            #pragma unroll
            for (int j = 0; j < 4; j++) acc[nt][j] = 0.f;

        // ---- K loop: 9 taps x 2 slices, base+imm LDS ----
        #pragma unroll
        for (int t = 0; t < 9; t++) {
            const int dOff = ((t / 3) * 34 + (t % 3)) * 32;
            uint2 x0 = *(const uint2*)(fb + aBase + dOff);
            uint2 x1 = *(const uint2*)(fb + aBase + dOff + 256);
            #pragma unroll
            for (int s = 0; s < 2; s++) {
                const int ks = t * 2 + s;
                uint32_t m0 = (uint32_t)(-((code[0] >> (t + 16 * s)) & 1));
                uint32_t m1 = (uint32_t)(-((code[1] >> (t + 16 * s)) & 1));
                uint32_t a0 = x0.x & m0;
                uint32_t a1 = x1.x & m1;
                uint32_t a2 = x0.y & m0;
                uint32_t a3 = x1.y & m1;
                #pragma unroll
                for (int nt = 0; nt < 4; nt++) {
                    uint2 bv = *(const uint2*)(Bb + ks * 1024 + nt * 256 + bBase);
                    MMA16816(acc[nt], a0, a1, a2, a3, bv.x, bv.y);
                }
            }
        }

        // ---- epilogue: direct STG (8-lane 32B sectors) ----
        const int h = h0 + row;
        const int wpx = w0 + colhalf * 16 + g;
        #pragma unroll
        for (int nt = 0; nt < 4; nt++) {
            int oc = nt * 8 + t4 * 2;
            float* op = out + (((size_t)b * 32 + oc) * 512 + h) * 512;
            op[wpx]              = acc[nt][0];
            op[262144 + wpx]     = acc[nt][1];
            op[wpx + 8]          = acc[nt][2];
            op[262144 + wpx + 8] = acc[nt][3];
        }
        __syncthreads();   // ftile/dt free before next tile's staging
    }
}

extern "C" void kernel_launch(void* const* d_in, const int* in_sizes, int n_in,
                              void* d_out, int out_size) {
    const float* feat  = (const float*)d_in[0];   // (4,16,512,512) f32
    const int*   depth = (const int*)d_in[1];     // (4,512,512) i32
    const float* wgt   = (const float*)d_in[2];   // (32,16,3,3,3) f32
    float* out = (float*)d_out;                   // (4,32,512,512) f32

    int dev = 0, sms = 148;
    cudaGetDevice(&dev);
    cudaDeviceGetAttribute(&sms, cudaDevAttrMultiProcessorCount, dev);
    int grid = 3 * sms;
    if (grid > N_TILES) grid = N_TILES;
    depconv_hmma<<<grid, 256>>>(feat, depth, wgt, out);
}

// round 16
// speedup vs baseline: 1.2162x; 1.1727x over previous
#include <cuda_runtime.h>
#include <cuda_fp16.h>
#include <cstdint>

static constexpr int N_TILES = 4096;   // 16 (w) x 64 (h) x 4 (batch), 32x8 tiles

#define MMA16816(c, a0, a1, a2, a3, b0, b1) \
    asm volatile( \
        "mma.sync.aligned.m16n8k16.row.col.f32.f16.f16.f32 " \
        "{%0,%1,%2,%3}, {%4,%5,%6,%7}, {%8,%9}, {%0,%1,%2,%3};" \
        : "+f"((c)[0]), "+f"((c)[1]), "+f"((c)[2]), "+f"((c)[3]) \
        : "r"(a0), "r"(a1), "r"(a2), "r"(a3), "r"(b0), "r"(b1))

__global__ __launch_bounds__(256, 2)
void depconv_hmma(const float* __restrict__ feat,
                  const int* __restrict__ depth,
                  const float* __restrict__ wgt,
                  float* __restrict__ out) {
    // ftile[pix][ch]: pix = rr*34+cc (10x34 halo), 16 fp16 channels (32B/px)
    __shared__ __align__(16) unsigned short ftile[340 * 16];     // 10880 B
    // Bsm[ks][n][ch]: ks = t*2+s (18), n = oc (32), ch = ic (16)
    __shared__ __align__(16) unsigned short Bsm[18 * 32 * 16];   // 18432 B
    __shared__ int dt[340];                                      // 1360 B

    const int tid  = threadIdx.x;
    const int wid  = tid >> 5;        // 8 warps
    const int lane = tid & 31;
    const int g    = lane >> 2;       // fragment group 0..7
    const int t4   = lane & 3;

    const int rp = wid >> 1;          // row pair 0..3 (rows 2rp, 2rp+1)
    const int ch = wid & 1;           // 16-px column half

    // ---- build B once per CTA (fp16) ----
    for (int idx = tid; idx < 9216; idx += 256) {
        int ks = idx >> 9, rem = idx & 511;
        int n = rem >> 4, i = rem & 15;
        int t = ks >> 1, s = ks & 1;
        float v = wgt[(n * 16 + i) * 27 + s * 9 + t];
        Bsm[idx] = __half_as_ushort(__float2half_rn(v));
    }
    __syncthreads();

    const char* fb = (const char*)ftile;
    const char* Bb = (const char*)Bsm;

    // mtile mt -> pixel row 2rp+mt, cols ch*16 + {g, g+8}
    uint32_t aBase[2];
    #pragma unroll
    for (int mt = 0; mt < 2; mt++)
        aBase[mt] = (uint32_t)((((2 * rp + mt) * 34) + ch * 16 + g) * 32 + t4 * 8);
    const uint32_t bBase = (uint32_t)(g * 32 + t4 * 8);

    const int ic2 = tid & 7;      // channel-pair for staging
    const int pr  = tid >> 3;     // pixel lane 0..31 for staging

    for (int tile = blockIdx.x; tile < N_TILES; tile += gridDim.x) {
        const int twi = tile & 15, thi = (tile >> 4) & 63, b = tile >> 10;
        const int h0 = thi * 8, w0 = twi * 32;

        // ---- stage depth halo (10 x 34 = 340) ----
        for (int idx = tid; idx < 340; idx += 256) {
            int r = idx / 34, cc = idx - r * 34;
            int h = h0 - 1 + r, w = w0 - 1 + cc;
            int v = 0;
            if ((unsigned)h < 512u && (unsigned)w < 512u)
                v = depth[(b * 512 + h) * 512 + w];
            dt[idx] = v;
        }
        // ---- stage features as fp16 pairs; 32 pixel-lanes x 8 ch-pairs ----
        {
            const float* fp0 = feat + ((size_t)b * 16 + 2 * ic2) * 262144;
            #pragma unroll
            for (int pix = pr; pix < 340; pix += 32) {
                int r = pix / 34, cc = pix - r * 34;
                int h = h0 - 1 + r, w = w0 - 1 + cc;
                float v0 = 0.f, v1 = 0.f;
                if ((unsigned)h < 512u && (unsigned)w < 512u) {
                    v0 = fp0[h * 512 + w];
                    v1 = fp0[262144 + h * 512 + w];
                }
                __half2 hv = __floats2half2_rn(v0, v1);
                *(uint32_t*)((char*)ftile + pix * 32 + ic2 * 4) =
                    *reinterpret_cast<uint32_t*>(&hv);
            }
        }
        __syncthreads();

        // ---- gating codes: 2 mtiles x 2 fragment rows (pixels g, g+8) ----
        int code[2][2];
        #pragma unroll
        for (int mt = 0; mt < 2; mt++) {
            #pragma unroll
            for (int p = 0; p < 2; p++) {
                int pc = ch * 16 + g + p * 8;
                int rr = 2 * rp + mt;
                int dcc = dt[(rr + 1) * 34 + pc + 1];
                int A = 0, Bc = 0;
                #pragma unroll
                for (int t = 0; t < 9; t++) {
                    int dn = dt[(rr + t / 3) * 34 + pc + t % 3];
                    int diff = dn - dcc;
                    A  |= (diff == -1) ? (1 << t) : 0;
                    Bc |= (diff == 0) ? (1 << t) : 0;
                }
                code[mt][p] = A | (Bc << 16);
            }
        }

        float acc[2][4][4];
        #pragma unroll
        for (int mt = 0; mt < 2; mt++)
            #pragma unroll
            for (int nt = 0; nt < 4; nt++)
                #pragma unroll
                for (int j = 0; j < 4; j++) acc[mt][nt][j] = 0.f;

        // ---- K loop: 9 taps x 2 slices; B read once per (ks,nt), 2 mtiles ----
        #pragma unroll
        for (int t = 0; t < 9; t++) {
            const int dOff = ((t / 3) * 34 + (t % 3)) * 32;
            uint2 x0[2], x1[2];
            #pragma unroll
            for (int mt = 0; mt < 2; mt++) {
                x0[mt] = *(const uint2*)(fb + aBase[mt] + dOff);
                x1[mt] = *(const uint2*)(fb + aBase[mt] + dOff + 256);
            }
            #pragma unroll
            for (int s = 0; s < 2; s++) {
                const int ks = t * 2 + s;
                uint32_t a[2][4];
                #pragma unroll
                for (int mt = 0; mt < 2; mt++) {
                    uint32_t m0 = (uint32_t)(-((code[mt][0] >> (t + 16 * s)) & 1));
                    uint32_t m1 = (uint32_t)(-((code[mt][1] >> (t + 16 * s)) & 1));
                    a[mt][0] = x0[mt].x & m0;
                    a[mt][1] = x1[mt].x & m1;
                    a[mt][2] = x0[mt].y & m0;
                    a[mt][3] = x1[mt].y & m1;
                }
                #pragma unroll
                for (int nt = 0; nt < 4; nt++) {
                    uint2 bv = *(const uint2*)(Bb + ks * 1024 + nt * 256 + bBase);
                    MMA16816(acc[0][nt], a[0][0], a[0][1], a[0][2], a[0][3], bv.x, bv.y);
                    MMA16816(acc[1][nt], a[1][0], a[1][1], a[1][2], a[1][3], bv.x, bv.y);
                }
            }
        }

        // ---- epilogue: direct STG (8-lane 32B sectors) ----
        #pragma unroll
        for (int mt = 0; mt < 2; mt++) {
            const int h = h0 + 2 * rp + mt;
            const int wpx = w0 + ch * 16 + g;
            #pragma unroll
            for (int nt = 0; nt < 4; nt++) {
                int oc = nt * 8 + t4 * 2;
                float* op = out + (((size_t)b * 32 + oc) * 512 + h) * 512;
                op[wpx]              = acc[mt][nt][0];
                op[262144 + wpx]     = acc[mt][nt][1];
                op[wpx + 8]          = acc[mt][nt][2];
                op[262144 + wpx + 8] = acc[mt][nt][3];
            }
        }
        __syncthreads();   // ftile/dt free before next tile's staging
    }
}

extern "C" void kernel_launch(void* const* d_in, const int* in_sizes, int n_in,
                              void* d_out, int out_size) {
    const float* feat  = (const float*)d_in[0];   // (4,16,512,512) f32
    const int*   depth = (const int*)d_in[1];     // (4,512,512) i32
    const float* wgt   = (const float*)d_in[2];   // (32,16,3,3,3) f32
    float* out = (float*)d_out;                   // (4,32,512,512) f32

    int dev = 0, sms = 148;
    cudaGetDevice(&dev);
    cudaDeviceGetAttribute(&sms, cudaDevAttrMultiProcessorCount, dev);
    int grid = 2 * sms;
    if (grid > N_TILES) grid = N_TILES;
    depconv_hmma<<<grid, 256>>>(feat, depth, wgt, out);
}